// round 3
// baseline (speedup 1.0000x reference)
#include <cuda_runtime.h>
#include <math.h>
#include <float.h>

// Problem constants (fixed by dataset)
#define C_DIM   300
#define A_DIM   32
#define XSTR    600            // X row = [options(300) | cards(300)]
#define C_PAD   306            // Wt row pad: even (8B align) + 2-way-max bank conflicts
#define APT_PAD 12             // apt row pad: 48B => 16B aligned float4 rows
#define WARPS   8
#define RPW     8              // rows per warp
#define RPB     (WARPS*RPW)    // 64 rows per block

#define SMEM_FLOATS (C_DIM*A_DIM + A_DIM*C_PAD + WARPS*A_DIM*APT_PAD)
#define SMEM_BYTES  (SMEM_FLOATS * 4)

typedef unsigned long long u64;

// ---- packed f32x2 helpers (Blackwell FFMA2 path; only reachable via PTX) ----
__device__ __forceinline__ u64 pack2(float x, float y) {
    u64 r; asm("mov.b64 %0, {%1,%2};" : "=l"(r) : "f"(x), "f"(y)); return r;
}
__device__ __forceinline__ u64 dup2(float x) { return pack2(x, x); }
__device__ __forceinline__ void unpack2(u64 p, float &x, float &y) {
    asm("mov.b64 {%0,%1}, %2;" : "=f"(x), "=f"(y) : "l"(p));
}
__device__ __forceinline__ void fma2(u64 &d, u64 a, u64 b) {
    asm("fma.rn.f32x2 %0, %1, %2, %0;" : "+l"(d) : "l"(a), "l"(b));
}

__device__ __forceinline__ float signf(float x) {
    return (x > 0.f) ? 1.f : ((x < 0.f) ? -1.f : 0.f);
}

extern __shared__ __align__(16) float smem[];

__global__ void __launch_bounds__(256)
draftbot_kernel(const float* __restrict__ X, const float* __restrict__ W,
                float* __restrict__ out)
{
    float* Ws  = smem;                       // [C][A]  a-contiguous (phase 1)
    float* Wt  = smem + C_DIM * A_DIM;       // [A][C_PAD] c-contiguous (phase 2)
    float* apt = Wt + A_DIM * C_PAD;         // [WARPS][A][APT_PAD] transposed ap

    const int tid = threadIdx.x;

    // ---- stage W: direct copy (coalesced float4) ----
    {
        const float4* W4  = reinterpret_cast<const float4*>(W);
        float4*       Ws4 = reinterpret_cast<float4*>(Ws);
        #pragma unroll 2
        for (int i = tid; i < (C_DIM * A_DIM) / 4; i += 256) Ws4[i] = W4[i];
    }
    // ---- stage W transposed: Wt[a][c] = W[c][a]; coalesced reads ----
    {
        int a = tid & 31;
        for (int c = tid >> 5; c < C_DIM; c += 8)
            Wt[a * C_PAD + c] = W[c * A_DIM + a];
    }
    __syncthreads();

    const int warp = tid >> 5;
    const int lane = tid & 31;
    const int rg   = lane >> 3;   // 0..3 : row-pair group
    const int ag   = lane & 7;    // 0..7 : a-quad group
    const int row0 = blockIdx.x * RPB + warp * RPW;   // warp's first global row

    float* aw = apt + warp * (A_DIM * APT_PAD);

    // ================= Phase 1: ap = cards @ W + 1 =================
    // lane computes a-quad [4ag..4ag+3] for rows {2rg, 2rg+1}
    {
        const float4* c0p = reinterpret_cast<const float4*>(
            X + (size_t)(row0 + 2 * rg)     * XSTR + C_DIM);
        const float4* c1p = reinterpret_cast<const float4*>(
            X + (size_t)(row0 + 2 * rg + 1) * XSTR + C_DIM);

        u64 a00 = 0, a01 = 0, a10 = 0, a11 = 0;

        #pragma unroll 5
        for (int c4 = 0; c4 < C_DIM / 4; c4++) {
            float4 v0 = c0p[c4];
            float4 v1 = c1p[c4];
            float e0[4] = {v0.x, v0.y, v0.z, v0.w};
            float e1[4] = {v1.x, v1.y, v1.z, v1.w};
            const float* wbase = Ws + (c4 * 4) * A_DIM + 4 * ag;
            #pragma unroll
            for (int k = 0; k < 4; k++) {
                const u64* wp = reinterpret_cast<const u64*>(wbase + k * A_DIM);
                u64 wlo = wp[0], whi = wp[1];        // one LDS.128
                u64 d0 = dup2(e0[k]);
                u64 d1 = dup2(e1[k]);
                fma2(a00, d0, wlo);  fma2(a01, d0, whi);
                fma2(a10, d1, wlo);  fma2(a11, d1, whi);
            }
        }

        // write ap (transposed) to shared: apt[a][m] = acc + 1
        float x, y;
        unpack2(a00, x, y);
        aw[(4*ag+0)*APT_PAD + 2*rg]     = x + 1.f;
        aw[(4*ag+1)*APT_PAD + 2*rg]     = y + 1.f;
        unpack2(a01, x, y);
        aw[(4*ag+2)*APT_PAD + 2*rg]     = x + 1.f;
        aw[(4*ag+3)*APT_PAD + 2*rg]     = y + 1.f;
        unpack2(a10, x, y);
        aw[(4*ag+0)*APT_PAD + 2*rg + 1] = x + 1.f;
        aw[(4*ag+1)*APT_PAD + 2*rg + 1] = y + 1.f;
        unpack2(a11, x, y);
        aw[(4*ag+2)*APT_PAD + 2*rg + 1] = x + 1.f;
        aw[(4*ag+3)*APT_PAD + 2*rg + 1] = y + 1.f;
    }
    __syncwarp();

    // ================= Phase 2: t = ap @ W^T =================
    // lane owns column-pairs c = 2*lane + 64*j, j = 0..4 (j=4 predicated)
    const bool j4ok = (2 * lane + 256) < C_DIM;   // lanes 0..21

    u64 acc[RPW][5];
    #pragma unroll
    for (int m = 0; m < RPW; m++)
        #pragma unroll
        for (int j = 0; j < 5; j++) acc[m][j] = 0ull;

    #pragma unroll 4
    for (int a = 0; a < A_DIM; a++) {
        const float* ar = aw + a * APT_PAD;
        float4 lo = *reinterpret_cast<const float4*>(ar);      // broadcast
        float4 hi = *reinterpret_cast<const float4*>(ar + 4);  // broadcast
        u64 apd[RPW] = { dup2(lo.x), dup2(lo.y), dup2(lo.z), dup2(lo.w),
                         dup2(hi.x), dup2(hi.y), dup2(hi.z), dup2(hi.w) };

        const float* wr = Wt + a * C_PAD + 2 * lane;
        u64 w0  = *reinterpret_cast<const u64*>(wr);
        u64 w1  = *reinterpret_cast<const u64*>(wr + 64);
        u64 w2v = *reinterpret_cast<const u64*>(wr + 128);
        u64 w3  = *reinterpret_cast<const u64*>(wr + 192);
        u64 w4v = j4ok ? *reinterpret_cast<const u64*>(wr + 256) : 0ull;

        #pragma unroll
        for (int m = 0; m < RPW; m++) {
            fma2(acc[m][0], apd[m], w0);
            fma2(acc[m][1], apd[m], w1);
            fma2(acc[m][2], apd[m], w2v);
            fma2(acc[m][3], apd[m], w3);
            fma2(acc[m][4], apd[m], w4v);
        }
    }

    // ====== Phase 3: scores = options * t; sign-aware log-softmax; store ======
    const int cb = 2 * lane;
    #pragma unroll
    for (int m = 0; m < RPW; m++) {
        const int row = row0 + m;
        const float* optp = X + (size_t)row * XSTR + cb;   // options block
        float v[10];
        #pragma unroll
        for (int j = 0; j < 5; j++) {
            float tx, ty; unpack2(acc[m][j], tx, ty);
            if (j < 4 || j4ok) {
                float2 o = *reinterpret_cast<const float2*>(optp + 64 * j);
                v[2*j]   = o.x * tx;
                v[2*j+1] = o.y * ty;
            } else {
                v[2*j] = 0.f; v[2*j+1] = 0.f;
            }
        }

        // row max (b) over valid columns only
        float mx = -FLT_MAX;
        #pragma unroll
        for (int i = 0; i < 10; i++)
            if (i < 8 || j4ok) mx = fmaxf(mx, v[i]);
        #pragma unroll
        for (int off = 16; off; off >>= 1)
            mx = fmaxf(mx, __shfl_xor_sync(0xffffffffu, mx, off));

        // ssum = sum s * exp(x - b*s)   (s=0 entries contribute exactly 0)
        float ss = 0.f;
        #pragma unroll
        for (int i = 0; i < 10; i++) {
            if (i < 8 || j4ok) {
                float x = v[i];
                float s = signf(x);
                ss += s * __expf(fmaf(-mx, s, x));
            }
        }
        #pragma unroll
        for (int off = 16; off; off >>= 1)
            ss += __shfl_xor_sync(0xffffffffu, ss, off);

        float lse = __logf(ss);

        float* op = out + (size_t)row * C_DIM + cb;
        #pragma unroll
        for (int j = 0; j < 5; j++) {
            if (j < 4 || j4ok) {
                float2 r;
                {
                    float x = v[2*j];   float s = signf(x);
                    r.x = (s != 0.f) ? s * (fmaf(-mx, s, x) - lse) : 0.f;
                }
                {
                    float x = v[2*j+1]; float s = signf(x);
                    r.y = (s != 0.f) ? s * (fmaf(-mx, s, x) - lse) : 0.f;
                }
                *reinterpret_cast<float2*>(op + 64 * j) = r;
            }
        }
    }
}

extern "C" void kernel_launch(void* const* d_in, const int* in_sizes, int n_in,
                              void* d_out, int out_size)
{
    const float* X = (const float*)d_in[0];
    const float* W = (const float*)d_in[1];
    float* out     = (float*)d_out;

    const int rows = in_sizes[0] / XSTR;        // 65536
    const int grid = rows / RPB;                // 1024

    cudaFuncSetAttribute(draftbot_kernel,
                         cudaFuncAttributeMaxDynamicSharedMemorySize, SMEM_BYTES);
    draftbot_kernel<<<grid, 256, SMEM_BYTES>>>(X, W, out);
}